// round 15
// baseline (speedup 1.0000x reference)
#include <cuda_runtime.h>
#include <cstdint>

#define VOCAB 256
#define D 512
#define A 64
#define BB 8
#define LL 2048
#define LN_EPS 1e-5f
#define LUTW 264   // lut row stride: 256 real cols + sentinel(256)=0 + pad

// ---------------- scratch (device globals; no allocations) ----------------
__device__ float4 g_h4[VOCAB * 128];       // h row-major: [v][d/4]
__device__ float g_q[VOCAB * A];
__device__ float g_kT[A * VOCAB];
__device__ float g_gate[VOCAB];
__device__ float g_logit[VOCAB * VOCAB];
__device__ float g_vprob[VOCAB * VOCAB];
__device__ float g_score[VOCAB * VOCAB];
__device__ float g_cnt[BB * VOCAB];

// pipeline flags (zero-init; reset by last writer block each launch)
__device__ int g_f1, g_f2, g_f3, g_f4;

// ---------------- helpers ----------------
__device__ __forceinline__ float warpSum(float v) {
    #pragma unroll
    for (int o = 16; o > 0; o >>= 1) v += __shfl_xor_sync(0xFFFFFFFFu, v, o);
    return v;
}
__device__ __forceinline__ float warpMax(float v) {
    #pragma unroll
    for (int o = 16; o > 0; o >>= 1) v = fmaxf(v, __shfl_xor_sync(0xFFFFFFFFu, v, o));
    return v;
}
__device__ __forceinline__ float blockSum256(float v, float* sh) {
    int w = threadIdx.x >> 5, l = threadIdx.x & 31;
    v = warpSum(v);
    if (l == 0) sh[w] = v;
    __syncthreads();
    if (w == 0) {
        float x = (l < 8) ? sh[l] : 0.f;
        x = warpSum(x);
        if (l == 0) sh[0] = x;
    }
    __syncthreads();
    float r = sh[0];
    __syncthreads();
    return r;
}
__device__ __forceinline__ float blockMax256(float v, float* sh) {
    int w = threadIdx.x >> 5, l = threadIdx.x & 31;
    v = warpMax(v);
    if (l == 0) sh[w] = v;
    __syncthreads();
    if (w == 0) {
        float x = (l < 8) ? sh[l] : -1e30f;
        x = warpMax(x);
        if (l == 0) sh[0] = x;
    }
    __syncthreads();
    float r = sh[0];
    __syncthreads();
    return r;
}
__device__ __forceinline__ void waitFlag(int* f, int target) {
    if (threadIdx.x == 0) {
        while (atomicAdd(f, 0) < target) __nanosleep(128);
    }
    __syncthreads();     // broadcast + acquire for the block
}
__device__ __forceinline__ void signalFlag(int* f) {
    __threadfence();     // make this block's table writes visible device-wide
    __syncthreads();
    if (threadIdx.x == 0) atomicAdd(f, 1);
}

// ---------------- the whole model in one kernel ----------------------------
// bids [0,8):      per-batch histogram            -> f1
// bids [8,40):     LN (8 rows per block)          -> f1  (target 40)
// bids [40,840):   proj GEMM (waits f1)           -> f2  (target 800)
// bids [840,1096): vocab softmax + score (f2)     -> f3  (target 256)
// bids [1096,2120): AT/LM/attn writer (waits f3); last one resets flags
__global__ void __launch_bounds__(256, 4)
k_all(const int* __restrict__ tokens, const int* __restrict__ plen,
      const float* __restrict__ E,
      const float* __restrict__ eg, const float* __restrict__ eb,
      const float* __restrict__ fg, const float* __restrict__ fb,
      const float* __restrict__ qw, const float* __restrict__ qb,
      const float* __restrict__ kw, const float* __restrict__ kb,
      const float* __restrict__ gw, const float* __restrict__ gb,
      float* __restrict__ out, int has_gate, int has_attn) {
    __shared__ __align__(16) unsigned char sraw[18048];
    int bid = blockIdx.x, tid = threadIdx.x, w = tid >> 5, l = tid & 31;

    // ============ stage 1a: histogram ============
    if (bid < 8) {
        int* c = (int*)sraw;
        int b = bid;
        c[tid] = 0;
        __syncthreads();
        int P = plen[b];
        #pragma unroll
        for (int it = 0; it < 8; it++) {
            int i = it * 256 + tid;
            int tk = tokens[b * LL + i];
            if (i < P && tk != 0) atomicAdd(&c[tk & 255], 1);
        }
        __syncthreads();
        g_cnt[b * VOCAB + tid] = (float)c[tid];
        signalFlag(&g_f1);
        return;
    }

    // ============ stage 1b: double LayerNorm ============
    if (bid < 40) {
        int v = (bid - 8) * 8 + w;
        const float4* E4 = (const float4*)E;
        float4 ef[4];
        #pragma unroll
        for (int j = 0; j < 4; j++) ef[j] = E4[v * 128 + l + 32 * j];
        float s = 0.f;
        #pragma unroll
        for (int j = 0; j < 4; j++) s += ef[j].x + ef[j].y + ef[j].z + ef[j].w;
        float mu = warpSum(s) * (1.f / D);
        float vv = 0.f;
        #pragma unroll
        for (int j = 0; j < 4; j++) {
            ef[j].x -= mu; ef[j].y -= mu; ef[j].z -= mu; ef[j].w -= mu;
            vv += ef[j].x * ef[j].x + ef[j].y * ef[j].y
                + ef[j].z * ef[j].z + ef[j].w * ef[j].w;
        }
        float inv = rsqrtf(warpSum(vv) * (1.f / D) + LN_EPS);
        {
            const float4* G = (const float4*)eg;
            const float4* Bv = (const float4*)eb;
            #pragma unroll
            for (int j = 0; j < 4; j++) {
                float4 g4 = G[l + 32 * j], b4 = Bv[l + 32 * j];
                ef[j].x = ef[j].x * inv * g4.x + b4.x;
                ef[j].y = ef[j].y * inv * g4.y + b4.y;
                ef[j].z = ef[j].z * inv * g4.z + b4.z;
                ef[j].w = ef[j].w * inv * g4.w + b4.w;
            }
        }
        s = 0.f;
        #pragma unroll
        for (int j = 0; j < 4; j++) s += ef[j].x + ef[j].y + ef[j].z + ef[j].w;
        mu = warpSum(s) * (1.f / D);
        vv = 0.f;
        #pragma unroll
        for (int j = 0; j < 4; j++) {
            ef[j].x -= mu; ef[j].y -= mu; ef[j].z -= mu; ef[j].w -= mu;
            vv += ef[j].x * ef[j].x + ef[j].y * ef[j].y
                + ef[j].z * ef[j].z + ef[j].w * ef[j].w;
        }
        inv = rsqrtf(warpSum(vv) * (1.f / D) + LN_EPS);
        {
            const float4* G = (const float4*)fg;
            const float4* Bv = (const float4*)fb;
            #pragma unroll
            for (int j = 0; j < 4; j++) {
                float4 g4 = G[l + 32 * j], b4 = Bv[l + 32 * j];
                float4 hv;
                hv.x = ef[j].x * inv * g4.x + b4.x;
                hv.y = ef[j].y * inv * g4.y + b4.y;
                hv.z = ef[j].z * inv * g4.z + b4.z;
                hv.w = ef[j].w * inv * g4.w + b4.w;
                g_h4[v * 128 + l + 32 * j] = hv;
            }
        }
        signalFlag(&g_f1);
        return;
    }

    // ============ stage 2: proj GEMM ============
    if (bid < 840) {
        float4* hs4 = (float4*)sraw;       // 8 KB tile
        int pb = bid - 40;
        int v0 = (pb & 31) * 8;
        int obase = (pb >> 5) * 16;

        int olist[2];
        bool oval[2];
        float bias[2];
        const float4* wrow4[2];
        #pragma unroll
        for (int oi = 0; oi < 2; oi++) {
            int o = obase + w * 2 + oi;
            oval[oi] = (o <= 384);
            int oe = oval[oi] ? o : 384;
            olist[oi] = oe;
            const float* wr;
            if (oe < 256)      { wr = E + oe * D;          bias[oi] = 0.f; }
            else if (oe < 320) { wr = qw + (oe - 256) * D; bias[oi] = qb[oe - 256]; }
            else if (oe < 384) { wr = kw + (oe - 320) * D; bias[oi] = kb[oe - 320]; }
            else               { wr = gw;                  bias[oi] = gb[0]; }
            wrow4[oi] = (const float4*)wr;
        }
        // weights are kernel inputs: load BEFORE the wait to overlap latency
        float4 e4[2][4];
        #pragma unroll
        for (int oi = 0; oi < 2; oi++)
            #pragma unroll
            for (int jj = 0; jj < 4; jj++)
                e4[oi][jj] = wrow4[oi][l + 32 * jj];

        waitFlag(&g_f1, 40);

        #pragma unroll
        for (int i = 0; i < 4; i++)
            hs4[tid + 256 * i] = g_h4[v0 * 128 + tid + 256 * i];
        __syncthreads();

        float acc[8][2];
        #pragma unroll
        for (int r = 0; r < 8; r++) { acc[r][0] = 0.f; acc[r][1] = 0.f; }

        #pragma unroll
        for (int r = 0; r < 8; r++) {
            #pragma unroll
            for (int jj = 0; jj < 4; jj++) {
                float4 h4 = hs4[r * 128 + l + 32 * jj];
                #pragma unroll
                for (int oi = 0; oi < 2; oi++) {
                    acc[r][oi] += e4[oi][jj].x * h4.x + e4[oi][jj].y * h4.y
                                + e4[oi][jj].z * h4.z + e4[oi][jj].w * h4.w;
                }
            }
        }

        #pragma unroll
        for (int oi = 0; oi < 2; oi++) {
            #pragma unroll
            for (int r = 0; r < 8; r++) {
                float s = warpSum(acc[r][oi]);
                if (l == 0 && oval[oi]) {
                    int o = olist[oi];
                    int v = v0 + r;
                    if (o < 256)      g_logit[v * VOCAB + o] = s;
                    else if (o < 320) g_q[v * A + (o - 256)] = s + bias[oi];
                    else if (o < 384) g_kT[(o - 320) * VOCAB + v] = s + bias[oi];
                    else              g_gate[v] = 1.f / (1.f + __expf(-(s + bias[oi])));
                }
            }
        }
        signalFlag(&g_f2);
        return;
    }

    // ============ stage 3: vocab softmax + score ============
    if (bid < 1096) {
        float* red = (float*)sraw;
        float* qs  = (float*)(sraw + 128);
        int qv = bid - 840;

        waitFlag(&g_f2, 800);

        float lo = g_logit[qv * VOCAB + tid];
        if (tid < A) qs[tid] = g_q[qv * A + tid];
        __syncthreads();
        float s = 0.f;
        #pragma unroll
        for (int d = 0; d < A; d++) s += qs[d] * g_kT[d * VOCAB + tid];
        g_score[qv * VOCAB + tid] = s * 0.125f;
        float m = blockMax256(lo, red);
        float e = __expf(lo - m);
        float Z = blockSum256(e, red);
        g_vprob[qv * VOCAB + tid] = e * __frcp_rn(Z);
        signalFlag(&g_f3);
        return;
    }

    // ============ stage 4: AT/LM/attn writer ============
    {
        float (*lut)[LUTW] = reinterpret_cast<float(*)[LUTW]>(sraw);
        float* scnt = (float*)(sraw + 16896);
        float* gts  = (float*)(sraw + 17920);
        int*   qvs  = (int*)(sraw + 17984);

        int idx = bid - 1096;
        int b = idx >> 7, t0 = (idx & 127) * 16;
        int P = plen[b];

        // token loads are kernel inputs: issue BEFORE the wait
        if (tid < 16) qvs[tid] = tokens[b * LL + t0 + tid] & 255;
        const int4* tg = (const int4*)(tokens + b * LL);
        int4 tkA = tg[tid], tkB = tg[tid + 256];
        {
            int sA = tid * 4, sB = (tid + 256) * 4;
            tkA.x = (sA + 0 < P) ? (tkA.x & 255) : 256;
            tkA.y = (sA + 1 < P) ? (tkA.y & 255) : 256;
            tkA.z = (sA + 2 < P) ? (tkA.z & 255) : 256;
            tkA.w = (sA + 3 < P) ? (tkA.w & 255) : 256;
            tkB.x = (sB + 0 < P) ? (tkB.x & 255) : 256;
            tkB.y = (sB + 1 < P) ? (tkB.y & 255) : 256;
            tkB.z = (sB + 2 < P) ? (tkB.z & 255) : 256;
            tkB.w = (sB + 3 < P) ? (tkB.w & 255) : 256;
        }

        waitFlag(&g_f3, 256);           // implies f2 (gate) and f1 (cnt) done

        scnt[tid] = g_cnt[b * VOCAB + tid];
        if (tid < 16) gts[tid] = g_gate[qvs[tid]];
        __syncthreads();

        // ---- AT rows: warp w computes rows w and w+8 (shuffles only) ----
        #pragma unroll
        for (int jj = 0; jj < 2; jj++) {
            int j = w + jj * 8;
            int qv = qvs[j];
            float sv[8], cf[8];
            float mx = -1e30f;
            #pragma unroll
            for (int m = 0; m < 8; m++) {
                int v = l + 32 * m;
                sv[m] = g_score[qv * VOCAB + v];
                cf[m] = scnt[v];
                mx = fmaxf(mx, cf[m] > 0.f ? sv[m] : -1e30f);
            }
            mx = warpMax(mx);
            float ex[8], z = 0.f;
            #pragma unroll
            for (int m = 0; m < 8; m++) {
                ex[m] = __expf(sv[m] - mx);
                z += cf[m] * ex[m];
            }
            z = warpSum(z);
            float invz = __frcp_rn(z);
            #pragma unroll
            for (int m = 0; m < 8; m++) {
                int v = l + 32 * m;
                float at = ex[m] * invz;
                if (v == 0) at = 0.f;            // PAD column masked
                lut[j][v] = at;
            }
            if (l == 0) lut[j][256] = 0.f;       // sentinel for s >= P
        }
        __syncthreads();

        float* out_lm   = out;
        float* out_gate = out + (size_t)BB * LL * VOCAB;
        float* out_attn = out_gate + (size_t)BB * LL;

        if (has_gate && tid < 16) out_gate[b * LL + t0 + tid] = gts[tid];

        // ---- LM: vectorized, thread = (col-group, row-group) ----
        {
            int c = tid & 63;
            int jg = tid >> 6;
            float4 cn4 = ((const float4*)scnt)[c];
            #pragma unroll
            for (int k = 0; k < 4; k++) {
                int j = jg * 4 + k;
                int qv = qvs[j];
                float gt = gts[j], og = 1.f - gt;
                float4 lv = *(const float4*)&lut[j][4 * c];
                float4 pv = ((const float4*)(g_vprob + qv * VOCAB))[c];
                float4 m4;
                m4.x = __logf(fmaxf(gt * pv.x + og * (cn4.x * lv.x), 1e-12f));
                m4.y = __logf(fmaxf(gt * pv.y + og * (cn4.y * lv.y), 1e-12f));
                m4.z = __logf(fmaxf(gt * pv.z + og * (cn4.z * lv.z), 1e-12f));
                m4.w = __logf(fmaxf(gt * pv.w + og * (cn4.w * lv.w), 1e-12f));
                __stcs((float4*)(out_lm + ((size_t)(b * LL + t0 + j)) * VOCAB) + c, m4);
            }
        }

        // ---- attn streaming: branch-free scalar gather ----
        if (has_attn) {
            #pragma unroll
            for (int j = 0; j < 16; j++) {
                const float* L = lut[j];
                float4* orow = (float4*)(out_attn + ((size_t)(b * LL + t0 + j)) * LL);
                float4 o;
                o.x = L[tkA.x]; o.y = L[tkA.y]; o.z = L[tkA.z]; o.w = L[tkA.w];
                __stcs(orow + tid, o);
                o.x = L[tkB.x]; o.y = L[tkB.y]; o.z = L[tkB.z]; o.w = L[tkB.w];
                __stcs(orow + 256 + tid, o);
            }
        }

        // done-counter; last writer resets all flags for the next launch
        __syncthreads();
        if (tid == 0) {
            int old = atomicAdd(&g_f4, 1);
            if (old == 1023) { g_f1 = 0; g_f2 = 0; g_f3 = 0; g_f4 = 0; }
        }
    }
}

// ---------------- launch ----------------
extern "C" void kernel_launch(void* const* d_in, const int* in_sizes, int n_in,
                              void* d_out, int out_size) {
    const int*   tokens = (const int*)d_in[0];
    const int*   plen   = (const int*)d_in[1];
    const float* E      = (const float*)d_in[2];
    const float* en_g   = (const float*)d_in[3];
    const float* en_b   = (const float*)d_in[4];
    const float* fn_g   = (const float*)d_in[5];
    const float* fn_b   = (const float*)d_in[6];
    const float* q_w    = (const float*)d_in[7];
    const float* q_b    = (const float*)d_in[8];
    const float* k_w    = (const float*)d_in[9];
    const float* k_b    = (const float*)d_in[10];
    const float* g_w    = (const float*)d_in[11];
    const float* g_b    = (const float*)d_in[12];

    const long long lm_sz   = (long long)BB * LL * VOCAB;
    const long long gate_sz = (long long)BB * LL;
    const long long attn_sz = (long long)BB * LL * LL;
    int has_gate = (out_size >= lm_sz + gate_sz) ? 1 : 0;
    int has_attn = (out_size >= lm_sz + gate_sz + attn_sz) ? 1 : 0;

    k_all<<<2120, 256>>>(tokens, plen, E, en_g, en_b, fn_g, fn_b,
                         q_w, q_b, k_w, k_b, g_w, g_b,
                         (float*)d_out, has_gate, has_attn);
}

// round 17
// speedup vs baseline: 1.0437x; 1.0437x over previous
#include <cuda_runtime.h>
#include <cstdint>

#define VOCAB 256
#define D 512
#define A 64
#define BB 8
#define LL 2048
#define LN_EPS 1e-5f
#define LUTW 264   // lut row stride: 256 real cols + sentinel(256)=0 + pad

// ---------------- scratch (device globals; no allocations) ----------------
__device__ float4 g_h4[VOCAB * 128];       // h row-major: [v][d/4]
__device__ float g_q[VOCAB * A];
__device__ float g_kT[A * VOCAB];
__device__ float g_gate[VOCAB];
__device__ float g_logit[VOCAB * VOCAB];
__device__ float g_vprob[VOCAB * VOCAB];
__device__ float g_score[VOCAB * VOCAB];
__device__ float g_cnt[BB * VOCAB];

// pipeline flags (zero-init; reset by last writer block each launch)
__device__ int g_f1, g_f3, g_f4;

// ---------------- helpers ----------------
__device__ __forceinline__ float warpSum(float v) {
    #pragma unroll
    for (int o = 16; o > 0; o >>= 1) v += __shfl_xor_sync(0xFFFFFFFFu, v, o);
    return v;
}
__device__ __forceinline__ float warpMax(float v) {
    #pragma unroll
    for (int o = 16; o > 0; o >>= 1) v = fmaxf(v, __shfl_xor_sync(0xFFFFFFFFu, v, o));
    return v;
}
__device__ __forceinline__ float blockSum256(float v, float* sh) {
    int w = threadIdx.x >> 5, l = threadIdx.x & 31;
    v = warpSum(v);
    if (l == 0) sh[w] = v;
    __syncthreads();
    if (w == 0) {
        float x = (l < 8) ? sh[l] : 0.f;
        x = warpSum(x);
        if (l == 0) sh[0] = x;
    }
    __syncthreads();
    float r = sh[0];
    __syncthreads();
    return r;
}
__device__ __forceinline__ float blockMax256(float v, float* sh) {
    int w = threadIdx.x >> 5, l = threadIdx.x & 31;
    v = warpMax(v);
    if (l == 0) sh[w] = v;
    __syncthreads();
    if (w == 0) {
        float x = (l < 8) ? sh[l] : -1e30f;
        x = warpMax(x);
        if (l == 0) sh[0] = x;
    }
    __syncthreads();
    float r = sh[0];
    __syncthreads();
    return r;
}
__device__ __forceinline__ void waitFlag(int* f, int target) {
    if (threadIdx.x == 0) {
        while (atomicAdd(f, 0) < target) __nanosleep(64);
    }
    __syncthreads();     // broadcast + acquire for the block
}
__device__ __forceinline__ void signalFlag(int* f) {
    __threadfence();     // make this block's table writes visible device-wide
    __syncthreads();
    if (threadIdx.x == 0) atomicAdd(f, 1);
}

// ================= kernel A: hist + LN (bids 0-39) -> proj (40-839) =======
__global__ void __launch_bounds__(256)
kA(const int* __restrict__ tokens, const int* __restrict__ plen,
   const float* __restrict__ E,
   const float* __restrict__ eg, const float* __restrict__ eb,
   const float* __restrict__ fg, const float* __restrict__ fb,
   const float* __restrict__ qw, const float* __restrict__ qb,
   const float* __restrict__ kw, const float* __restrict__ kb,
   const float* __restrict__ gw, const float* __restrict__ gb) {
    __shared__ __align__(16) unsigned char sraw[16384];   // proj tile = 16 KB
    int bid = blockIdx.x, tid = threadIdx.x, w = tid >> 5, l = tid & 31;

    if (bid < 8) {                      // ---- histogram ----
        int* c = (int*)sraw;
        int b = bid;
        c[tid] = 0;
        __syncthreads();
        int P = plen[b];
        #pragma unroll
        for (int it = 0; it < 8; it++) {
            int i = it * 256 + tid;
            int tk = tokens[b * LL + i];
            if (i < P && tk != 0) atomicAdd(&c[tk & 255], 1);
        }
        __syncthreads();
        g_cnt[b * VOCAB + tid] = (float)c[tid];
        signalFlag(&g_f1);
        return;
    }

    if (bid < 40) {                     // ---- double LayerNorm ----
        int v = (bid - 8) * 8 + w;
        const float4* E4 = (const float4*)E;
        float4 ef[4];
        #pragma unroll
        for (int j = 0; j < 4; j++) ef[j] = E4[v * 128 + l + 32 * j];
        float s = 0.f;
        #pragma unroll
        for (int j = 0; j < 4; j++) s += ef[j].x + ef[j].y + ef[j].z + ef[j].w;
        float mu = warpSum(s) * (1.f / D);
        float vv = 0.f;
        #pragma unroll
        for (int j = 0; j < 4; j++) {
            ef[j].x -= mu; ef[j].y -= mu; ef[j].z -= mu; ef[j].w -= mu;
            vv += ef[j].x * ef[j].x + ef[j].y * ef[j].y
                + ef[j].z * ef[j].z + ef[j].w * ef[j].w;
        }
        float inv = rsqrtf(warpSum(vv) * (1.f / D) + LN_EPS);
        {
            const float4* G = (const float4*)eg;
            const float4* Bv = (const float4*)eb;
            #pragma unroll
            for (int j = 0; j < 4; j++) {
                float4 g4 = G[l + 32 * j], b4 = Bv[l + 32 * j];
                ef[j].x = ef[j].x * inv * g4.x + b4.x;
                ef[j].y = ef[j].y * inv * g4.y + b4.y;
                ef[j].z = ef[j].z * inv * g4.z + b4.z;
                ef[j].w = ef[j].w * inv * g4.w + b4.w;
            }
        }
        s = 0.f;
        #pragma unroll
        for (int j = 0; j < 4; j++) s += ef[j].x + ef[j].y + ef[j].z + ef[j].w;
        mu = warpSum(s) * (1.f / D);
        vv = 0.f;
        #pragma unroll
        for (int j = 0; j < 4; j++) {
            ef[j].x -= mu; ef[j].y -= mu; ef[j].z -= mu; ef[j].w -= mu;
            vv += ef[j].x * ef[j].x + ef[j].y * ef[j].y
                + ef[j].z * ef[j].z + ef[j].w * ef[j].w;
        }
        inv = rsqrtf(warpSum(vv) * (1.f / D) + LN_EPS);
        {
            const float4* G = (const float4*)fg;
            const float4* Bv = (const float4*)fb;
            #pragma unroll
            for (int j = 0; j < 4; j++) {
                float4 g4 = G[l + 32 * j], b4 = Bv[l + 32 * j];
                float4 hv;
                hv.x = ef[j].x * inv * g4.x + b4.x;
                hv.y = ef[j].y * inv * g4.y + b4.y;
                hv.z = ef[j].z * inv * g4.z + b4.z;
                hv.w = ef[j].w * inv * g4.w + b4.w;
                g_h4[v * 128 + l + 32 * j] = hv;
            }
        }
        signalFlag(&g_f1);
        return;
    }

    // ---- proj GEMM (waits f1=40; weight loads issued first) ----
    {
        float4* hs4 = (float4*)sraw;    // 1024 float4 = 16 KB
        int pb = bid - 40;
        int v0 = (pb & 31) * 8;
        int obase = (pb >> 5) * 16;

        int olist[2];
        bool oval[2];
        float bias[2];
        const float4* wrow4[2];
        #pragma unroll
        for (int oi = 0; oi < 2; oi++) {
            int o = obase + w * 2 + oi;
            oval[oi] = (o <= 384);
            int oe = oval[oi] ? o : 384;
            olist[oi] = oe;
            const float* wr;
            if (oe < 256)      { wr = E + oe * D;          bias[oi] = 0.f; }
            else if (oe < 320) { wr = qw + (oe - 256) * D; bias[oi] = qb[oe - 256]; }
            else if (oe < 384) { wr = kw + (oe - 320) * D; bias[oi] = kb[oe - 320]; }
            else               { wr = gw;                  bias[oi] = gb[0]; }
            wrow4[oi] = (const float4*)wr;
        }
        float4 e4[2][4];
        #pragma unroll
        for (int oi = 0; oi < 2; oi++)
            #pragma unroll
            for (int jj = 0; jj < 4; jj++)
                e4[oi][jj] = wrow4[oi][l + 32 * jj];

        waitFlag(&g_f1, 40);

        #pragma unroll
        for (int i = 0; i < 4; i++)
            hs4[tid + 256 * i] = g_h4[v0 * 128 + tid + 256 * i];
        __syncthreads();

        float acc[8][2];
        #pragma unroll
        for (int r = 0; r < 8; r++) { acc[r][0] = 0.f; acc[r][1] = 0.f; }

        #pragma unroll
        for (int r = 0; r < 8; r++) {
            #pragma unroll
            for (int jj = 0; jj < 4; jj++) {
                float4 h4 = hs4[r * 128 + l + 32 * jj];
                #pragma unroll
                for (int oi = 0; oi < 2; oi++) {
                    acc[r][oi] += e4[oi][jj].x * h4.x + e4[oi][jj].y * h4.y
                                + e4[oi][jj].z * h4.z + e4[oi][jj].w * h4.w;
                }
            }
        }

        #pragma unroll
        for (int oi = 0; oi < 2; oi++) {
            #pragma unroll
            for (int r = 0; r < 8; r++) {
                float s = warpSum(acc[r][oi]);
                if (l == 0 && oval[oi]) {
                    int o = olist[oi];
                    int v = v0 + r;
                    if (o < 256)      g_logit[v * VOCAB + o] = s;
                    else if (o < 320) g_q[v * A + (o - 256)] = s + bias[oi];
                    else if (o < 384) g_kT[(o - 320) * VOCAB + v] = s + bias[oi];
                    else              g_gate[v] = 1.f / (1.f + __expf(-(s + bias[oi])));
                }
            }
        }
    }
}

// ========== kernel B: softmax+score (bids 0-255) -> writer (256-1279) ======
__global__ void __launch_bounds__(256)
kB(const int* __restrict__ tokens, const int* __restrict__ plen,
   float* __restrict__ out, int has_gate, int has_attn) {
    __shared__ __align__(16) unsigned char sraw[18048];
    int bid = blockIdx.x, tid = threadIdx.x, w = tid >> 5, l = tid & 31;

    if (bid < 256) {                    // ---- vocab softmax + score ----
        float* red = (float*)sraw;
        float* qs  = (float*)(sraw + 128);
        int qv = bid;
        float lo = g_logit[qv * VOCAB + tid];
        if (tid < A) qs[tid] = g_q[qv * A + tid];
        __syncthreads();
        float s = 0.f;
        #pragma unroll
        for (int d = 0; d < A; d++) s += qs[d] * g_kT[d * VOCAB + tid];
        g_score[qv * VOCAB + tid] = s * 0.125f;
        float m = blockMax256(lo, red);
        float e = __expf(lo - m);
        float Z = blockSum256(e, red);
        g_vprob[qv * VOCAB + tid] = e * __frcp_rn(Z);
        signalFlag(&g_f3);
        return;
    }

    // ---- writer: AT/LM/attn (waits f3=256; token LDGs issued first) ----
    {
        float (*lut)[LUTW] = reinterpret_cast<float(*)[LUTW]>(sraw);
        float* scnt = (float*)(sraw + 16896);
        float* gts  = (float*)(sraw + 17920);
        int*   qvs  = (int*)(sraw + 17984);

        int idx = bid - 256;
        int b = idx >> 7, t0 = (idx & 127) * 16;
        int P = plen[b];

        if (tid < 16) qvs[tid] = tokens[b * LL + t0 + tid] & 255;
        const int4* tg = (const int4*)(tokens + b * LL);
        int4 tkA = tg[tid], tkB = tg[tid + 256];
        {
            int sA = tid * 4, sB = (tid + 256) * 4;
            tkA.x = (sA + 0 < P) ? (tkA.x & 255) : 256;
            tkA.y = (sA + 1 < P) ? (tkA.y & 255) : 256;
            tkA.z = (sA + 2 < P) ? (tkA.z & 255) : 256;
            tkA.w = (sA + 3 < P) ? (tkA.w & 255) : 256;
            tkB.x = (sB + 0 < P) ? (tkB.x & 255) : 256;
            tkB.y = (sB + 1 < P) ? (tkB.y & 255) : 256;
            tkB.z = (sB + 2 < P) ? (tkB.z & 255) : 256;
            tkB.w = (sB + 3 < P) ? (tkB.w & 255) : 256;
        }
        float cnt_reg = g_cnt[b * VOCAB + tid];   // kA output: ready pre-wait

        waitFlag(&g_f3, 256);

        scnt[tid] = cnt_reg;
        if (tid < 16) gts[tid] = g_gate[qvs[tid]];
        __syncthreads();

        // ---- AT rows: warp w computes rows w and w+8 (shuffles only) ----
        #pragma unroll
        for (int jj = 0; jj < 2; jj++) {
            int j = w + jj * 8;
            int qv = qvs[j];
            float sv[8], cf[8];
            float mx = -1e30f;
            #pragma unroll
            for (int m = 0; m < 8; m++) {
                int v = l + 32 * m;
                sv[m] = g_score[qv * VOCAB + v];
                cf[m] = scnt[v];
                mx = fmaxf(mx, cf[m] > 0.f ? sv[m] : -1e30f);
            }
            mx = warpMax(mx);
            float ex[8], z = 0.f;
            #pragma unroll
            for (int m = 0; m < 8; m++) {
                ex[m] = __expf(sv[m] - mx);
                z += cf[m] * ex[m];
            }
            z = warpSum(z);
            float invz = __frcp_rn(z);
            #pragma unroll
            for (int m = 0; m < 8; m++) {
                int v = l + 32 * m;
                float at = ex[m] * invz;
                if (v == 0) at = 0.f;            // PAD column masked
                lut[j][v] = at;
            }
            if (l == 0) lut[j][256] = 0.f;       // sentinel for s >= P
        }
        __syncthreads();

        float* out_lm   = out;
        float* out_gate = out + (size_t)BB * LL * VOCAB;
        float* out_attn = out_gate + (size_t)BB * LL;

        if (has_gate && tid < 16) out_gate[b * LL + t0 + tid] = gts[tid];

        // ---- LM: vectorized, thread = (col-group, row-group) ----
        {
            int c = tid & 63;
            int jg = tid >> 6;
            float4 cn4 = ((const float4*)scnt)[c];
            #pragma unroll
            for (int k = 0; k < 4; k++) {
                int j = jg * 4 + k;
                int qv = qvs[j];
                float gt = gts[j], og = 1.f - gt;
                float4 lv = *(const float4*)&lut[j][4 * c];
                float4 pv = ((const float4*)(g_vprob + qv * VOCAB))[c];
                float4 m4;
                m4.x = __logf(fmaxf(gt * pv.x + og * (cn4.x * lv.x), 1e-12f));
                m4.y = __logf(fmaxf(gt * pv.y + og * (cn4.y * lv.y), 1e-12f));
                m4.z = __logf(fmaxf(gt * pv.z + og * (cn4.z * lv.z), 1e-12f));
                m4.w = __logf(fmaxf(gt * pv.w + og * (cn4.w * lv.w), 1e-12f));
                __stcs((float4*)(out_lm + ((size_t)(b * LL + t0 + j)) * VOCAB) + c, m4);
            }
        }

        // ---- attn streaming: branch-free scalar gather ----
        if (has_attn) {
            #pragma unroll
            for (int j = 0; j < 16; j++) {
                const float* L = lut[j];
                float4* orow = (float4*)(out_attn + ((size_t)(b * LL + t0 + j)) * LL);
                float4 o;
                o.x = L[tkA.x]; o.y = L[tkA.y]; o.z = L[tkA.z]; o.w = L[tkA.w];
                __stcs(orow + tid, o);
                o.x = L[tkB.x]; o.y = L[tkB.y]; o.z = L[tkB.z]; o.w = L[tkB.w];
                __stcs(orow + 256 + tid, o);
            }
        }

        // done-counter; last writer resets all flags for the next launch
        __syncthreads();
        if (tid == 0) {
            int old = atomicAdd(&g_f4, 1);
            if (old == 1023) { g_f1 = 0; g_f3 = 0; g_f4 = 0; }
        }
    }
}

// ---------------- launch ----------------
extern "C" void kernel_launch(void* const* d_in, const int* in_sizes, int n_in,
                              void* d_out, int out_size) {
    const int*   tokens = (const int*)d_in[0];
    const int*   plen   = (const int*)d_in[1];
    const float* E      = (const float*)d_in[2];
    const float* en_g   = (const float*)d_in[3];
    const float* en_b   = (const float*)d_in[4];
    const float* fn_g   = (const float*)d_in[5];
    const float* fn_b   = (const float*)d_in[6];
    const float* q_w    = (const float*)d_in[7];
    const float* q_b    = (const float*)d_in[8];
    const float* k_w    = (const float*)d_in[9];
    const float* k_b    = (const float*)d_in[10];
    const float* g_w    = (const float*)d_in[11];
    const float* g_b    = (const float*)d_in[12];

    const long long lm_sz   = (long long)BB * LL * VOCAB;
    const long long gate_sz = (long long)BB * LL;
    const long long attn_sz = (long long)BB * LL * LL;
    int has_gate = (out_size >= lm_sz + gate_sz) ? 1 : 0;
    int has_attn = (out_size >= lm_sz + gate_sz + attn_sz) ? 1 : 0;

    kA<<<840, 256>>>(tokens, plen, E, en_g, en_b, fn_g, fn_b,
                     q_w, q_b, k_w, k_b, g_w, g_b);
    kB<<<1280, 256>>>(tokens, plen, (float*)d_out, has_gate, has_attn);
}